// round 15
// baseline (speedup 1.0000x reference)
#include <cuda_runtime.h>
#include <math.h>

// Problem constants
static constexpr int   N_NODES  = 200000;
static constexpr int   N_USERS  = 100000;
static constexpr int   DIM      = 64;
static constexpr int   LAYERS   = 3;
static constexpr int   E_EDGES  = 3000000;
static constexpr int   N_LINK   = 100000;
static constexpr int   EMB_COLS = (LAYERS + 1) * DIM;     // 256
static constexpr int   ELLW     = 48;                     // ELL row width
static constexpr int   OVF_CAP  = 4096;

// ---------------------------------------------------------------------------
// Scratch. Feature tables have a ZERO GUARD ROW at index 0 (node v -> row v+1).
// Guard rows are never written (zero from .bss forever).
//
// ELL adjacency: g_ell_x[v*48 + p] = src+1 for p < deg(v); pad slots up to
// ceil16(deg) (capped at 48) are zeroed each call by k_prep. Edges beyond 48
// per node go to an overflow list; the fused layer kernel scans it for any
// node with deg > 48 (correct for arbitrary inputs; empty in practice).
//
// Ping-pong feature tables: layer l reads g_xs[l%2]/g_xt[l%2] (layer 0 reads
// g_xs0 for both graphs) and writes the other pair — required because the
// fused kernel reads and writes feature tables in the same launch.
// ---------------------------------------------------------------------------
__device__ int    g_cnt_s[N_NODES],  g_cnt_t[N_NODES];
__device__ int    g_ell_s[(size_t)N_NODES * ELLW];
__device__ int    g_ell_t[(size_t)N_NODES * ELLW];
__device__ int    g_ovfn_s, g_ovfn_t;
__device__ int2   g_ovf_s[OVF_CAP], g_ovf_t[OVF_CAP];     // {dst, src}
__device__ float  g_invdeg_s[N_NODES], g_invdeg_t[N_NODES];
__device__ float  g_xs0[(size_t)(N_NODES + 1) * DIM];     // +guard
__device__ float  g_xt0[(size_t)(N_NODES + 1) * DIM];     // +guard
__device__ float  g_xs1[(size_t)(N_NODES + 1) * DIM];     // +guard
__device__ float  g_xt1[(size_t)(N_NODES + 1) * DIM];     // +guard
__device__ float  g_embs[(size_t)(N_NODES + 1) * EMB_COLS]; // [emb|x1|x2|x3]

// ---------------------------------------------------------------------------
// (1) One-pass ELL build for BOTH graphs: slot = atomicAdd(cnt[dst]).
// ---------------------------------------------------------------------------
__global__ void k_build(const int* __restrict__ s_src, const int* __restrict__ s_dst,
                        const int* __restrict__ t_src, const int* __restrict__ t_dst) {
    int e = blockIdx.x * blockDim.x + threadIdx.x;
    if (e >= E_EDGES) return;
    {
        int d = s_dst[e], s = s_src[e];
        int p = atomicAdd(&g_cnt_s[d], 1);
        if (p < ELLW) g_ell_s[(size_t)d * ELLW + p] = s + 1;
        else { int o = atomicAdd(&g_ovfn_s, 1); if (o < OVF_CAP) g_ovf_s[o] = make_int2(d, s); }
    }
    {
        int d = t_dst[e], s = t_src[e];
        int p = atomicAdd(&g_cnt_t[d], 1);
        if (p < ELLW) g_ell_t[(size_t)d * ELLW + p] = s + 1;
        else { int o = atomicAdd(&g_ovfn_t, 1); if (o < OVF_CAP) g_ovf_t[o] = make_int2(d, s); }
    }
}

// ---------------------------------------------------------------------------
// (2) Prep: invdeg; zero ELL pad slots [deg, min(ceil16(deg),48));
// copy emb into g_embs column block 0 and the layer-0 gather table g_xs0.
// ---------------------------------------------------------------------------
__global__ void k_prep(const float4* __restrict__ emb4) {
    int i = blockIdx.x * blockDim.x + threadIdx.x;
    if (i < N_NODES) {
        int ds = g_cnt_s[i], dt = g_cnt_t[i];
        g_invdeg_s[i] = 1.f / fmaxf((float)ds, 1.f);
        g_invdeg_t[i] = 1.f / fmaxf((float)dt, 1.f);
        int ps = min((ds + 15) & ~15, ELLW);
        int pt = min((dt + 15) & ~15, ELLW);
        for (int p = ds; p < ps; p++) g_ell_s[(size_t)i * ELLW + p] = 0;
        for (int p = dt; p < pt; p++) g_ell_t[(size_t)i * ELLW + p] = 0;
    }
    const long NF4 = (long)N_NODES * (DIM / 4);
    long stride = (long)gridDim.x * blockDim.x;
    for (long j = (long)blockIdx.x * blockDim.x + threadIdx.x; j < NF4; j += stride) {
        long v = j >> 4;
        int  d = (int)(j & 15);
        float4 f = emb4[j];
        reinterpret_cast<float4*>(g_embs)[(v + 1) * (EMB_COLS / 4) + d] = f;
        reinterpret_cast<float4*>(g_xs0)[(v + 1) * (DIM / 4) + d] = f;
    }
}

// ---------------------------------------------------------------------------
// Gather one node's neighbor mean numerator (half-warp collective).
// Main loop over <=48 padded ELL slots; overflow list scanned only when
// deg > ELLW (exact correctness for any input).
// ---------------------------------------------------------------------------
__device__ __forceinline__ float4 gather_node(
    const float* __restrict__ x, const int* __restrict__ ell, int d, int v,
    const int2* __restrict__ ovf, const int* __restrict__ ovfn_p,
    unsigned hm, int h, int c)
{
    int p16 = min((d + 15) & ~15, ELLW);
    const int* row = ell + (size_t)v * ELLW;
    float4 acc = make_float4(0.f, 0.f, 0.f, 0.f);
    for (int j0 = 0; j0 < p16; j0 += 16) {
        int idx = __ldg(&row[j0 + c]);
        #pragma unroll
        for (int j = 0; j < 16; j++) {
            int s = __shfl_sync(hm, idx, h * 16 + j);
            float4 vv = __ldg(reinterpret_cast<const float4*>(x + (size_t)s * DIM) + c);
            acc.x += vv.x; acc.y += vv.y; acc.z += vv.z; acc.w += vv.w;
        }
    }
    if (d > ELLW) {                                   // exact overflow path
        int n = min(*ovfn_p, OVF_CAP);
        for (int i = 0; i < n; i++) {
            int2 p = ovf[i];
            if (p.x == v) {
                float4 vv = __ldg(reinterpret_cast<const float4*>(
                                      x + (size_t)(p.y + 1) * DIM) + c);
                acc.x += vv.x; acc.y += vv.y; acc.z += vv.z; acc.w += vv.w;
            }
        }
    }
    return acc;
}

// ---------------------------------------------------------------------------
// (3..5) FUSED LAYER: source gather + target gather + combine in one kernel.
// Block = 16 nodes (half-warp per node). Means staged in 8KB smem instead of
// 102MB global arrays. Blocks fully in the item range skip the W tile load.
// Last layer (write_next=0): item nodes skip the target gather entirely.
// ---------------------------------------------------------------------------
__global__ void __launch_bounds__(256)
k_layer(const float* __restrict__ xin_s, const float* __restrict__ xin_t,
        float* __restrict__ xout_s, float* __restrict__ xout_t,
        const float* __restrict__ mix_w, const float* __restrict__ mix_b,
        int layer, int write_next)
{
    __shared__ float4 WT4[64 * 32];    // 32 KB: W packed as k-pairs x out-pairs
    __shared__ float  BB[64];
    __shared__ float  s_ms[16][64];    // 4 KB source means
    __shared__ float  s_mt[16][64];    // 4 KB target means

    int nodeBase = blockIdx.x * 16;
    bool hasUsers = nodeBase < N_USERS;      // block-uniform (100000 % 16 == 0)
    int tid = threadIdx.x;

    if (hasUsers) {
        const float* W = mix_w + (size_t)layer * 64 * 128;
        for (int i = tid; i < 64 * 32; i += 256) {
            int k2 = i >> 5, ln = i & 31;
            WT4[i] = make_float4(W[ln * 128 + 2 * k2],     W[(ln + 32) * 128 + 2 * k2],
                                 W[ln * 128 + 2 * k2 + 1], W[(ln + 32) * 128 + 2 * k2 + 1]);
        }
        if (tid < 64) BB[tid] = mix_b[layer * 64 + tid];
    }

    int      lane = tid & 31;
    int      w    = tid >> 5;
    int      h    = lane >> 4;                  // half-warp id
    int      c    = lane & 15;                  // float4 chunk / ell slot
    unsigned hm   = h ? 0xFFFF0000u : 0x0000FFFFu;
    int      li   = 2 * w + h;                  // local node 0..15
    int      v    = nodeBase + li;

    // --- source gather ---
    {
        int ds = __ldg(&g_cnt_s[v]);
        float4 a = gather_node(xin_s, g_ell_s, ds, v, g_ovf_s, &g_ovfn_s, hm, h, c);
        float iv = g_invdeg_s[v];
        *reinterpret_cast<float4*>(&s_ms[li][4 * c]) =
            make_float4(a.x * iv, a.y * iv, a.z * iv, a.w * iv);
    }
    // --- target gather (skipped for item blocks on the last layer) ---
    bool needT = write_next || hasUsers;        // block-uniform
    if (needT) {
        int dt = __ldg(&g_cnt_t[v]);
        float4 a = gather_node(xin_t, g_ell_t, dt, v, g_ovf_t, &g_ovfn_t, hm, h, c);
        float iv = g_invdeg_t[v];
        *reinterpret_cast<float4*>(&s_mt[li][4 * c]) =
            make_float4(a.x * iv, a.y * iv, a.z * iv, a.w * iv);
    }

    if (hasUsers) __syncthreads();              // WT4 ready (block-uniform path)
    else          __syncwarp();                 // s_ms/s_mt are warp-local

    // --- combine: each warp processes the 2 nodes its half-warps gathered ---
    #pragma unroll
    for (int n = 0; n < 2; n++) {
        int li2 = 2 * w + n;
        int v2  = nodeBase + li2;
        size_t base = (size_t)(v2 + 1) * DIM;

        float ms0 = s_ms[li2][lane];
        float ms1 = s_ms[li2][lane + 32];
        float mt0 = needT ? s_mt[li2][lane]      : 0.f;
        float mt1 = needT ? s_mt[li2][lane + 32] : 0.f;

        float o0, o1, t0, t1;
        if (hasUsers) {                          // all 16 nodes are users
            float a0 = BB[lane], a1 = BB[lane + 32];
            #pragma unroll
            for (int k2 = 0; k2 < 16; k2++) {
                float m0 = __shfl_sync(0xffffffffu, ms0, 2 * k2);
                float m1 = __shfl_sync(0xffffffffu, ms0, 2 * k2 + 1);
                float4 qv = WT4[k2 * 32 + lane];
                a0 += m0 * qv.x + m1 * qv.z;
                a1 += m0 * qv.y + m1 * qv.w;
            }
            #pragma unroll
            for (int k2 = 0; k2 < 16; k2++) {
                float m0 = __shfl_sync(0xffffffffu, ms1, 2 * k2);
                float m1 = __shfl_sync(0xffffffffu, ms1, 2 * k2 + 1);
                float4 qv = WT4[(16 + k2) * 32 + lane];
                a0 += m0 * qv.x + m1 * qv.z;
                a1 += m0 * qv.y + m1 * qv.w;
            }
            #pragma unroll
            for (int k2 = 0; k2 < 16; k2++) {
                float m0 = __shfl_sync(0xffffffffu, mt0, 2 * k2);
                float m1 = __shfl_sync(0xffffffffu, mt0, 2 * k2 + 1);
                float4 qv = WT4[(32 + k2) * 32 + lane];
                a0 += m0 * qv.x + m1 * qv.z;
                a1 += m0 * qv.y + m1 * qv.w;
            }
            #pragma unroll
            for (int k2 = 0; k2 < 16; k2++) {
                float m0 = __shfl_sync(0xffffffffu, mt1, 2 * k2);
                float m1 = __shfl_sync(0xffffffffu, mt1, 2 * k2 + 1);
                float4 qv = WT4[(48 + k2) * 32 + lane];
                a0 += m0 * qv.x + m1 * qv.z;
                a1 += m0 * qv.y + m1 * qv.w;
            }
            o0 = a0; o1 = a1; t0 = a0; t1 = a1;  // users: both paths = user_emb
        } else {
            o0 = ms0; o1 = ms1; t0 = mt0; t1 = mt1;
        }

        if (write_next) {
            xout_s[base + lane]      = o0;
            xout_s[base + 32 + lane] = o1;
            xout_t[base + lane]      = t0;
            xout_t[base + 32 + lane] = t1;
        }
        float* er = g_embs + (size_t)(v2 + 1) * EMB_COLS + (size_t)(layer + 1) * DIM;
        er[lane]      = o0;
        er[lane + 32] = o1;
    }
}

// ---------------------------------------------------------------------------
// Prediction head: warp per link, float4 loads (1-based rows, fp32).
// ---------------------------------------------------------------------------
__global__ void k_pred(const int* __restrict__ link,
                       const float* __restrict__ pred_w,
                       const float* __restrict__ pred_b,
                       float* __restrict__ out) {
    __shared__ float4 pw4[128];                       // 512 floats
    for (int i = threadIdx.x; i < 128; i += blockDim.x)
        pw4[i] = reinterpret_cast<const float4*>(pred_w)[i];
    __syncthreads();

    int lane = threadIdx.x & 31;
    int warp = threadIdx.x >> 5;
    int j = blockIdx.x * (blockDim.x >> 5) + warp;
    if (j >= N_LINK) return;

    int u  = __ldg(&link[j]) + 1;
    int it = __ldg(&link[N_LINK + j]) + 1;
    const float4* ue4 = reinterpret_cast<const float4*>(g_embs + (size_t)u  * EMB_COLS);
    const float4* ie4 = reinterpret_cast<const float4*>(g_embs + (size_t)it * EMB_COLS);

    float acc = 0.f;
    #pragma unroll
    for (int r = 0; r < 2; r++) {
        int idx = lane + r * 32;                      // 0..63
        float4 a = __ldg(&ue4[idx]);
        float4 w = pw4[idx];
        acc += a.x * w.x + a.y * w.y + a.z * w.z + a.w * w.w;
        float4 b = __ldg(&ie4[idx]);
        float4 w2 = pw4[64 + idx];
        acc += b.x * w2.x + b.y * w2.y + b.z * w2.z + b.w * w2.w;
    }

    #pragma unroll
    for (int o = 16; o > 0; o >>= 1) acc += __shfl_down_sync(0xffffffffu, acc, o);

    if (lane == 0) {
        float z = acc + pred_b[0];
        z = (z >= 0.f) ? z : 0.01f * z;
        out[j] = 1.f / (1.f + expf(-z));
    }
}

// ---------------------------------------------------------------------------
// Tail: restore zero state (counts + overflow counters) for the next call.
// ---------------------------------------------------------------------------
__global__ void k_tail() {
    int stride = gridDim.x * blockDim.x;
    int t0 = blockIdx.x * blockDim.x + threadIdx.x;
    for (int i = t0; i < N_NODES; i += stride) { g_cnt_s[i] = 0; g_cnt_t[i] = 0; }
    if (t0 == 0) { g_ovfn_s = 0; g_ovfn_t = 0; }
}

// ---------------------------------------------------------------------------
// Launch: 7 kernels total (was 17).
// ---------------------------------------------------------------------------
extern "C" void kernel_launch(void* const* d_in, const int* in_sizes, int n_in,
                              void* d_out, int out_size) {
    const int*   sei    = (const int*)  d_in[0];
    const int*   tei    = (const int*)  d_in[1];
    const int*   link   = (const int*)  d_in[2];
    const float* emb    = (const float*)d_in[3];
    const float* mix_w  = (const float*)d_in[4];
    const float* mix_b  = (const float*)d_in[5];
    const float* pred_w = (const float*)d_in[6];
    const float* pred_b = (const float*)d_in[7];
    float*       out    = (float*)d_out;

    const int* s_src = sei;
    const int* s_dst = sei + E_EDGES;
    const int* t_src = tei;
    const int* t_dst = tei + E_EDGES;

    k_build<<<(E_EDGES + 255) / 256, 256>>>(s_src, s_dst, t_src, t_dst);
    k_prep <<<(N_NODES + 255) / 256, 256>>>(reinterpret_cast<const float4*>(emb));

    const int layer_blocks = N_NODES / 16;            // 12500

    for (int l = 0; l < LAYERS; l++) {
        // ping-pong: l0 reads xs0 (emb) for both graphs, writes xs1/xt1;
        // l1 reads xs1/xt1, writes xs0/xt0; l2 reads xs0/xt0, writes nothing.
        const float* in_s = (l % 2 == 0) ? g_xs0 : g_xs1;
        const float* in_t = (l == 0) ? g_xs0 : ((l % 2 == 0) ? g_xt0 : g_xt1);
        float*       out_s = (l % 2 == 0) ? g_xs1 : g_xs0;
        float*       out_t = (l % 2 == 0) ? g_xt1 : g_xt0;
        int write_next = (l < LAYERS - 1) ? 1 : 0;
        k_layer<<<layer_blocks, 256>>>(in_s, in_t, out_s, out_t,
                                       mix_w, mix_b, l, write_next);
    }

    k_pred<<<(N_LINK + 7) / 8, 256>>>(link, pred_w, pred_b, out);
    k_tail<<<4096, 256>>>();
}

// round 16
// speedup vs baseline: 4.3908x; 4.3908x over previous
#include <cuda_runtime.h>
#include <math.h>

// Problem constants
static constexpr int   N_NODES  = 200000;
static constexpr int   N_USERS  = 100000;
static constexpr int   DIM      = 64;
static constexpr int   LAYERS   = 3;
static constexpr int   E_EDGES  = 3000000;
static constexpr int   N_LINK   = 100000;
static constexpr int   EMB_COLS = (LAYERS + 1) * DIM;     // 256
static constexpr int   ELLW     = 48;                     // ELL row width
static constexpr int   OVF_CAP  = 4096;
static constexpr int   TILE_MID = N_NODES / 2;            // source-range tile split

// ---------------------------------------------------------------------------
// Scratch. Feature tables have a ZERO GUARD ROW at index 0 (node v -> row v+1).
// Guard rows are never written (zero from .bss forever).
//
// ELL adjacency: g_ell_x[v*48 + p] = src+1 for p < deg(v); pad slots up to
// ceil16(deg) (capped at 48) are zeroed each call by k_prep. Edges beyond 48
// per node go to an overflow list applied by k_ovf (correct for any input;
// empty in practice). cnt/ovf counters re-zeroed by k_tail each call.
//
// L2-TILED GATHER: each conv runs as 2 passes over source-row tiles
// [1, MID+1) and [MID+1, N+1) in (src+1) space. Out-of-tile entries are
// redirected branch-free to the guard row (adds 0). Pass 0 writes raw
// partial sums; pass 1 adds its partial, scales by invdeg, writes the mean.
// Per-pass gather slice = 25.5MB -> stays L2-resident for the whole pass.
// ---------------------------------------------------------------------------
__device__ int    g_cnt_s[N_NODES],  g_cnt_t[N_NODES];
__device__ int    g_ell_s[(size_t)N_NODES * ELLW];
__device__ int    g_ell_t[(size_t)N_NODES * ELLW];
__device__ int    g_ovfn_s, g_ovfn_t;
__device__ int2   g_ovf_s[OVF_CAP], g_ovf_t[OVF_CAP];     // {dst, src}
__device__ float  g_invdeg_s[N_NODES], g_invdeg_t[N_NODES];
__device__ float  g_means[(size_t)(N_NODES + 1) * DIM];       // +guard
__device__ float  g_meant[(size_t)(N_NODES + 1) * DIM];       // +guard
__device__ float  g_xs   [(size_t)(N_NODES + 1) * DIM];       // dense source gather
__device__ float  g_xt   [(size_t)(N_NODES + 1) * DIM];       // dense target gather
__device__ float  g_embs [(size_t)(N_NODES + 1) * EMB_COLS];  // [emb|x1|x2|x3]

// ---------------------------------------------------------------------------
// (1) One-pass ELL build for BOTH graphs: slot = atomicAdd(cnt[dst]).
// ---------------------------------------------------------------------------
__global__ void k_build(const int* __restrict__ s_src, const int* __restrict__ s_dst,
                        const int* __restrict__ t_src, const int* __restrict__ t_dst) {
    int e = blockIdx.x * blockDim.x + threadIdx.x;
    if (e >= E_EDGES) return;
    {
        int d = s_dst[e], s = s_src[e];
        int p = atomicAdd(&g_cnt_s[d], 1);
        if (p < ELLW) g_ell_s[(size_t)d * ELLW + p] = s + 1;
        else { int o = atomicAdd(&g_ovfn_s, 1); if (o < OVF_CAP) g_ovf_s[o] = make_int2(d, s); }
    }
    {
        int d = t_dst[e], s = t_src[e];
        int p = atomicAdd(&g_cnt_t[d], 1);
        if (p < ELLW) g_ell_t[(size_t)d * ELLW + p] = s + 1;
        else { int o = atomicAdd(&g_ovfn_t, 1); if (o < OVF_CAP) g_ovf_t[o] = make_int2(d, s); }
    }
}

// ---------------------------------------------------------------------------
// (2) Prep: invdeg; zero ELL pad slots [deg, min(ceil16(deg),48));
// copy emb into g_embs column block 0 and the layer-0 gather table g_xs.
// ---------------------------------------------------------------------------
__global__ void k_prep(const float4* __restrict__ emb4) {
    int i = blockIdx.x * blockDim.x + threadIdx.x;
    if (i < N_NODES) {
        int ds = g_cnt_s[i], dt = g_cnt_t[i];
        g_invdeg_s[i] = 1.f / fmaxf((float)ds, 1.f);
        g_invdeg_t[i] = 1.f / fmaxf((float)dt, 1.f);
        int ps = min((ds + 15) & ~15, ELLW);
        int pt = min((dt + 15) & ~15, ELLW);
        for (int p = ds; p < ps; p++) g_ell_s[(size_t)i * ELLW + p] = 0;
        for (int p = dt; p < pt; p++) g_ell_t[(size_t)i * ELLW + p] = 0;
    }
    const long NF4 = (long)N_NODES * (DIM / 4);
    long stride = (long)gridDim.x * blockDim.x;
    for (long j = (long)blockIdx.x * blockDim.x + threadIdx.x; j < NF4; j += stride) {
        long v = j >> 4;
        int  d = (int)(j & 15);
        float4 f = emb4[j];
        reinterpret_cast<float4*>(g_embs)[(v + 1) * (EMB_COLS / 4) + d] = f;
        reinterpret_cast<float4*>(g_xs)[(v + 1) * (DIM / 4) + d] = f;
    }
}

// ---------------------------------------------------------------------------
// (3..) L2-tiled gather conv: HALF-WARP per node, float4 (LDG.128) lanes.
// Gathers ONLY entries in [lo, hi) of (src+1) space; others redirected
// branch-free to the guard row (ISETP+SEL, no branch -> LDG batching kept).
// pass 0: store raw partial sum. pass 1: add partial, scale by invdeg, store.
// ---------------------------------------------------------------------------
__global__ void __launch_bounds__(256)
k_conv(const float* __restrict__ x,
       const int* __restrict__ cnt, const float* __restrict__ invd,
       const int* __restrict__ ell, float* __restrict__ om, int nN,
       int lo, unsigned span, int final_pass) {
    int w = (blockIdx.x * blockDim.x + threadIdx.x) >> 5;
    if (w >= nN / 2) return;
    int      lane = threadIdx.x & 31;
    int      h    = lane >> 4;                      // half-warp id
    int      c    = lane & 15;                      // float4 chunk / ell slot
    unsigned hm   = h ? 0xFFFF0000u : 0x0000FFFFu;
    int      v    = 2 * w + h;                      // 0-based node

    int d   = __ldg(&cnt[v]);
    int p16 = min((d + 15) & ~15, ELLW);
    const int* row = ell + (size_t)v * ELLW;

    float4 acc = make_float4(0.f, 0.f, 0.f, 0.f);

    for (int j0 = 0; j0 < p16; j0 += 16) {
        int idx = __ldg(&row[j0 + c]);              // 16 entries per half-warp
        #pragma unroll
        for (int j = 0; j < 16; j++) {
            int e = __shfl_sync(hm, idx, h * 16 + j);
            int s = ((unsigned)(e - lo) < span) ? e : 0;   // branch-free tile select
            float4 vv = __ldg(reinterpret_cast<const float4*>(
                                  x + (size_t)s * DIM) + c);
            acc.x += vv.x; acc.y += vv.y; acc.z += vv.z; acc.w += vv.w;
        }
    }

    float4* orow = reinterpret_cast<float4*>(om + (size_t)(v + 1) * DIM) + c;
    if (final_pass) {
        float4 prev = *orow;
        float  iv   = invd[v];
        *orow = make_float4((acc.x + prev.x) * iv, (acc.y + prev.y) * iv,
                            (acc.z + prev.z) * iv, (acc.w + prev.w) * iv);
    } else {
        *orow = acc;                                // raw partial sum
    }
}

// ---------------------------------------------------------------------------
// Overflow fix-up (runs after final conv passes; lists are empty in practice).
// ---------------------------------------------------------------------------
__global__ void k_ovf(const float* __restrict__ xs, const float* __restrict__ xt, int nT) {
    int ns = min(g_ovfn_s, OVF_CAP);
    for (int i = threadIdx.x; i < ns; i += blockDim.x) {
        int2 p = g_ovf_s[i];
        float iv = g_invdeg_s[p.x];
        const float* src = xs + (size_t)(p.y + 1) * DIM;
        float* dst = g_means + (size_t)(p.x + 1) * DIM;
        for (int c2 = 0; c2 < DIM; c2++) atomicAdd(&dst[c2], src[c2] * iv);
    }
    int nt = min(g_ovfn_t, OVF_CAP);
    for (int i = threadIdx.x; i < nt; i += blockDim.x) {
        int2 p = g_ovf_t[i];
        if (p.x >= nT) continue;
        float iv = g_invdeg_t[p.x];
        const float* src = xt + (size_t)(p.y + 1) * DIM;
        float* dst = g_meant + (size_t)(p.x + 1) * DIM;
        for (int c2 = 0; c2 < DIM; c2++) atomicAdd(&dst[c2], src[c2] * iv);
    }
}

// ---------------------------------------------------------------------------
// Combine: users get mix GEMM ue=[ms|mt]@W^T+b (fp32, float4-packed smem W).
// Writes dense next-layer gather tables g_xs/g_xt (skipped on last layer)
// and the g_embs slice (pred input).
// ---------------------------------------------------------------------------
__global__ void __launch_bounds__(256)
k_combine(const float* __restrict__ mix_w, const float* __restrict__ mix_b,
          int layer, int write_next) {
    // WT4[k2*32 + ln] = { W[ln][2k2], W[ln+32][2k2], W[ln][2k2+1], W[ln+32][2k2+1] }
    __shared__ float4 WT4[64 * 32];    // 32 KB
    __shared__ float  BB[64];

    const float* W = mix_w + (size_t)layer * 64 * 128;
    for (int i = threadIdx.x; i < 64 * 32; i += blockDim.x) {
        int k2 = i >> 5, ln = i & 31;
        WT4[i] = make_float4(W[ln * 128 + 2 * k2],     W[(ln + 32) * 128 + 2 * k2],
                             W[ln * 128 + 2 * k2 + 1], W[(ln + 32) * 128 + 2 * k2 + 1]);
    }
    if (threadIdx.x < 64) BB[threadIdx.x] = mix_b[layer * 64 + threadIdx.x];
    __syncthreads();

    int lane = threadIdx.x & 31;
    int warp = threadIdx.x >> 5;
    int wpb  = blockDim.x >> 5;

    for (int v = blockIdx.x * wpb + warp; v < N_NODES; v += gridDim.x * wpb) {
        size_t base = (size_t)(v + 1) * DIM;

        float ms0 = g_means[base + lane];
        float ms1 = g_means[base + 32 + lane];
        float mt0 = g_meant[base + lane];
        float mt1 = g_meant[base + 32 + lane];

        float o0, o1, t0, t1;
        if (v < N_USERS) {
            float a0 = BB[lane], a1 = BB[lane + 32];
            #pragma unroll
            for (int k2 = 0; k2 < 16; k2++) {
                float m0 = __shfl_sync(0xffffffffu, ms0, 2 * k2);
                float m1 = __shfl_sync(0xffffffffu, ms0, 2 * k2 + 1);
                float4 qv = WT4[k2 * 32 + lane];
                a0 += m0 * qv.x + m1 * qv.z;
                a1 += m0 * qv.y + m1 * qv.w;
            }
            #pragma unroll
            for (int k2 = 0; k2 < 16; k2++) {
                float m0 = __shfl_sync(0xffffffffu, ms1, 2 * k2);
                float m1 = __shfl_sync(0xffffffffu, ms1, 2 * k2 + 1);
                float4 qv = WT4[(16 + k2) * 32 + lane];
                a0 += m0 * qv.x + m1 * qv.z;
                a1 += m0 * qv.y + m1 * qv.w;
            }
            #pragma unroll
            for (int k2 = 0; k2 < 16; k2++) {
                float m0 = __shfl_sync(0xffffffffu, mt0, 2 * k2);
                float m1 = __shfl_sync(0xffffffffu, mt0, 2 * k2 + 1);
                float4 qv = WT4[(32 + k2) * 32 + lane];
                a0 += m0 * qv.x + m1 * qv.z;
                a1 += m0 * qv.y + m1 * qv.w;
            }
            #pragma unroll
            for (int k2 = 0; k2 < 16; k2++) {
                float m0 = __shfl_sync(0xffffffffu, mt1, 2 * k2);
                float m1 = __shfl_sync(0xffffffffu, mt1, 2 * k2 + 1);
                float4 qv = WT4[(48 + k2) * 32 + lane];
                a0 += m0 * qv.x + m1 * qv.z;
                a1 += m0 * qv.y + m1 * qv.w;
            }
            o0 = a0; o1 = a1; t0 = a0; t1 = a1;
        } else {
            o0 = ms0; o1 = ms1; t0 = mt0; t1 = mt1;
        }

        if (write_next) {
            g_xs[base + lane]      = o0;
            g_xs[base + 32 + lane] = o1;
            g_xt[base + lane]      = t0;
            g_xt[base + 32 + lane] = t1;
        }
        float* er = g_embs + (size_t)(v + 1) * EMB_COLS + (size_t)(layer + 1) * DIM;
        er[lane]      = o0;
        er[lane + 32] = o1;
    }
}

// ---------------------------------------------------------------------------
// Prediction head: warp per link, float4 loads (1-based rows, fp32).
// ---------------------------------------------------------------------------
__global__ void k_pred(const int* __restrict__ link,
                       const float* __restrict__ pred_w,
                       const float* __restrict__ pred_b,
                       float* __restrict__ out) {
    __shared__ float4 pw4[128];                       // 512 floats
    for (int i = threadIdx.x; i < 128; i += blockDim.x)
        pw4[i] = reinterpret_cast<const float4*>(pred_w)[i];
    __syncthreads();

    int lane = threadIdx.x & 31;
    int warp = threadIdx.x >> 5;
    int j = blockIdx.x * (blockDim.x >> 5) + warp;
    if (j >= N_LINK) return;

    int u  = __ldg(&link[j]) + 1;
    int it = __ldg(&link[N_LINK + j]) + 1;
    const float4* ue4 = reinterpret_cast<const float4*>(g_embs + (size_t)u  * EMB_COLS);
    const float4* ie4 = reinterpret_cast<const float4*>(g_embs + (size_t)it * EMB_COLS);

    float acc = 0.f;
    #pragma unroll
    for (int r = 0; r < 2; r++) {
        int idx = lane + r * 32;                      // 0..63
        float4 a = __ldg(&ue4[idx]);
        float4 w = pw4[idx];
        acc += a.x * w.x + a.y * w.y + a.z * w.z + a.w * w.w;
        float4 b = __ldg(&ie4[idx]);
        float4 w2 = pw4[64 + idx];
        acc += b.x * w2.x + b.y * w2.y + b.z * w2.z + b.w * w2.w;
    }

    #pragma unroll
    for (int o = 16; o > 0; o >>= 1) acc += __shfl_down_sync(0xffffffffu, acc, o);

    if (lane == 0) {
        float z = acc + pred_b[0];
        z = (z >= 0.f) ? z : 0.01f * z;
        out[j] = 1.f / (1.f + expf(-z));
    }
}

// ---------------------------------------------------------------------------
// Tail: restore zero state (counts + overflow counters) for the next call.
// ---------------------------------------------------------------------------
__global__ void k_tail() {
    int stride = gridDim.x * blockDim.x;
    int t0 = blockIdx.x * blockDim.x + threadIdx.x;
    for (int i = t0; i < N_NODES; i += stride) { g_cnt_s[i] = 0; g_cnt_t[i] = 0; }
    if (t0 == 0) { g_ovfn_s = 0; g_ovfn_t = 0; }
}

// ---------------------------------------------------------------------------
// Launch.
// ---------------------------------------------------------------------------
extern "C" void kernel_launch(void* const* d_in, const int* in_sizes, int n_in,
                              void* d_out, int out_size) {
    const int*   sei    = (const int*)  d_in[0];
    const int*   tei    = (const int*)  d_in[1];
    const int*   link   = (const int*)  d_in[2];
    const float* emb    = (const float*)d_in[3];
    const float* mix_w  = (const float*)d_in[4];
    const float* mix_b  = (const float*)d_in[5];
    const float* pred_w = (const float*)d_in[6];
    const float* pred_b = (const float*)d_in[7];
    float*       out    = (float*)d_out;

    const int* s_src = sei;
    const int* s_dst = sei + E_EDGES;
    const int* t_src = tei;
    const int* t_dst = tei + E_EDGES;

    k_build<<<(E_EDGES + 255) / 256, 256>>>(s_src, s_dst, t_src, t_dst);
    k_prep <<<(N_NODES + 255) / 256, 256>>>(reinterpret_cast<const float4*>(emb));

    // Tile bounds in (src+1) space: tile0 = [1, MID+1), tile1 = [MID+1, N+1)
    const int      lo0 = 1,            lo1 = 1 + TILE_MID;
    const unsigned sp0 = TILE_MID,     sp1 = N_NODES - TILE_MID;

    for (int l = 0; l < LAYERS; l++) {
        int gridN = (N_NODES / 2 * 32 + 255) / 256;
        // source conv: two L2-resident tile passes over g_xs
        k_conv<<<gridN, 256>>>(g_xs, g_cnt_s, g_invdeg_s, g_ell_s, g_means,
                               N_NODES, lo0, sp0, 0);
        k_conv<<<gridN, 256>>>(g_xs, g_cnt_s, g_invdeg_s, g_ell_s, g_means,
                               N_NODES, lo1, sp1, 1);
        // target conv: layer 0 gathers g_xs (same emb table); else g_xt.
        // Last layer: only user rows are ever consumed.
        const float* xt = (l == 0) ? g_xs : g_xt;
        int          nT = (l == LAYERS - 1) ? N_USERS : N_NODES;
        int gridT = (nT / 2 * 32 + 255) / 256;
        k_conv<<<gridT, 256>>>(xt, g_cnt_t, g_invdeg_t, g_ell_t, g_meant,
                               nT, lo0, sp0, 0);
        k_conv<<<gridT, 256>>>(xt, g_cnt_t, g_invdeg_t, g_ell_t, g_meant,
                               nT, lo1, sp1, 1);

        k_ovf<<<1, 256>>>(g_xs, xt, nT);

        k_combine<<<2960, 256>>>(mix_w, mix_b, l, l < LAYERS - 1 ? 1 : 0);
    }

    k_pred<<<(N_LINK + 7) / 8, 256>>>(link, pred_w, pred_b, out);
    k_tail<<<4096, 256>>>();
}

// round 17
// speedup vs baseline: 10.8923x; 2.4807x over previous
#include <cuda_runtime.h>
#include <math.h>

// Problem constants
static constexpr int   N_NODES  = 200000;
static constexpr int   N_USERS  = 100000;
static constexpr int   DIM      = 64;
static constexpr int   LAYERS   = 3;
static constexpr int   E_EDGES  = 3000000;
static constexpr int   N_LINK   = 100000;
static constexpr int   EMB_COLS = (LAYERS + 1) * DIM;     // 256
static constexpr int   ELLW     = 48;                     // ELL row width
static constexpr int   OVF_CAP  = 4096;

// ---------------------------------------------------------------------------
// Scratch. Feature tables have a ZERO GUARD ROW at index 0 (node v -> row v+1).
// Guard rows are never written (zero from .bss forever).
//
// ELL adjacency: g_ell_x[v*48 + p] = src+1 for p < deg(v); pad slots up to
// ceil16(deg) (capped at 48) are zeroed each call by k_prep. Edges beyond 48
// per node go to an overflow list applied by k_ovf (correct for any input;
// empty in practice). cnt/ovf counters re-zeroed by k_tail each call.
//
// L2 POLICY: the gather tables (g_xs/g_xt) keep DEFAULT cache policy (they
// are reused ~15x and must stay L2-resident). All single-use streams are
// demoted with .cs (evict-first): ELL reads, mean stores+reads, g_embs
// stores. This stops write-allocate/stream pollution from evicting the table.
//
// LINK MASK: g_need[v]=1 for nodes referenced by link (set-only, identical
// every call). Last layer: convs + combine skip unmarked nodes (their
// g_embs slice-3 rows are never read by pred).
// ---------------------------------------------------------------------------
__device__ int    g_cnt_s[N_NODES],  g_cnt_t[N_NODES];
__device__ int    g_ell_s[(size_t)N_NODES * ELLW];
__device__ int    g_ell_t[(size_t)N_NODES * ELLW];
__device__ int    g_ovfn_s, g_ovfn_t;
__device__ int2   g_ovf_s[OVF_CAP], g_ovf_t[OVF_CAP];     // {dst, src}
__device__ int    g_need[N_NODES];
__device__ float  g_invdeg_s[N_NODES], g_invdeg_t[N_NODES];
__device__ float  g_means[(size_t)(N_NODES + 1) * DIM];       // +guard
__device__ float  g_meant[(size_t)(N_NODES + 1) * DIM];       // +guard
__device__ float  g_xs   [(size_t)(N_NODES + 1) * DIM];       // dense source gather
__device__ float  g_xt   [(size_t)(N_NODES + 1) * DIM];       // dense target gather
__device__ float  g_embs [(size_t)(N_NODES + 1) * EMB_COLS];  // [emb|x1|x2|x3]

// ---------------------------------------------------------------------------
// (1) One-pass ELL build for BOTH graphs: slot = atomicAdd(cnt[dst]).
// ---------------------------------------------------------------------------
__global__ void k_build(const int* __restrict__ s_src, const int* __restrict__ s_dst,
                        const int* __restrict__ t_src, const int* __restrict__ t_dst) {
    int e = blockIdx.x * blockDim.x + threadIdx.x;
    if (e >= E_EDGES) return;
    {
        int d = __ldcs(&s_dst[e]), s = __ldcs(&s_src[e]);
        int p = atomicAdd(&g_cnt_s[d], 1);
        if (p < ELLW) g_ell_s[(size_t)d * ELLW + p] = s + 1;
        else { int o = atomicAdd(&g_ovfn_s, 1); if (o < OVF_CAP) g_ovf_s[o] = make_int2(d, s); }
    }
    {
        int d = __ldcs(&t_dst[e]), s = __ldcs(&t_src[e]);
        int p = atomicAdd(&g_cnt_t[d], 1);
        if (p < ELLW) g_ell_t[(size_t)d * ELLW + p] = s + 1;
        else { int o = atomicAdd(&g_ovfn_t, 1); if (o < OVF_CAP) g_ovf_t[o] = make_int2(d, s); }
    }
}

// ---------------------------------------------------------------------------
// (2) Prep: invdeg; zero ELL pad slots; mark link-referenced nodes; copy emb
// into g_embs block 0 (evict-first) and the layer-0 gather table g_xs.
// ---------------------------------------------------------------------------
__global__ void k_prep(const float4* __restrict__ emb4, const int* __restrict__ link) {
    int tot = gridDim.x * blockDim.x;
    int i   = blockIdx.x * blockDim.x + threadIdx.x;
    if (i < N_NODES) {
        int ds = g_cnt_s[i], dt = g_cnt_t[i];
        g_invdeg_s[i] = 1.f / fmaxf((float)ds, 1.f);
        g_invdeg_t[i] = 1.f / fmaxf((float)dt, 1.f);
        int ps = min((ds + 15) & ~15, ELLW);
        int pt = min((dt + 15) & ~15, ELLW);
        for (int p = ds; p < ps; p++) g_ell_s[(size_t)i * ELLW + p] = 0;
        for (int p = dt; p < pt; p++) g_ell_t[(size_t)i * ELLW + p] = 0;
    }
    // mark nodes referenced by link (set-only; identical every call)
    for (int j = i; j < 2 * N_LINK; j += tot)
        g_need[__ldcs(&link[j])] = 1;
    // emb -> g_embs (evict-first; pred-only) and g_xs (resident gather table)
    const long NF4 = (long)N_NODES * (DIM / 4);
    for (long j = i; j < NF4; j += tot) {
        long v = j >> 4;
        int  d = (int)(j & 15);
        float4 f = __ldcs(&emb4[j]);
        __stcs(&reinterpret_cast<float4*>(g_embs)[(v + 1) * (EMB_COLS / 4) + d], f);
        reinterpret_cast<float4*>(g_xs)[(v + 1) * (DIM / 4) + d] = f;
    }
}

// ---------------------------------------------------------------------------
// (3..) Gather conv: HALF-WARP per node, float4 (LDG.128) lanes, dense fp32
// tables. ELL reads evict-first; gathers default (table stays L2-resident);
// mean store evict-first. Optional link mask (half-warp-uniform skip).
// ---------------------------------------------------------------------------
__global__ void __launch_bounds__(256)
k_conv(const float* __restrict__ x,
       const int* __restrict__ cnt, const float* __restrict__ invd,
       const int* __restrict__ ell, float* __restrict__ om, int nN,
       const int* __restrict__ need, int use_mask) {
    int w = (blockIdx.x * blockDim.x + threadIdx.x) >> 5;
    if (w >= nN / 2) return;
    int      lane = threadIdx.x & 31;
    int      h    = lane >> 4;                      // half-warp id
    int      c    = lane & 15;                      // float4 chunk / ell slot
    unsigned hm   = h ? 0xFFFF0000u : 0x0000FFFFu;
    int      v    = 2 * w + h;                      // 0-based node

    if (use_mask && __ldg(&need[v]) == 0) return;   // half-warp uniform

    int d   = __ldg(&cnt[v]);
    int p16 = min((d + 15) & ~15, ELLW);
    const int* row = ell + (size_t)v * ELLW;

    float4 acc = make_float4(0.f, 0.f, 0.f, 0.f);

    for (int j0 = 0; j0 < p16; j0 += 16) {
        int idx = __ldcs(&row[j0 + c]);             // evict-first stream
        #pragma unroll
        for (int j = 0; j < 16; j++) {
            int s = __shfl_sync(hm, idx, h * 16 + j);
            float4 vv = __ldg(reinterpret_cast<const float4*>(
                                  x + (size_t)s * DIM) + c);
            acc.x += vv.x; acc.y += vv.y; acc.z += vv.z; acc.w += vv.w;
        }
    }

    float iv = invd[v];
    float4 o = make_float4(acc.x * iv, acc.y * iv, acc.z * iv, acc.w * iv);
    __stcs(&reinterpret_cast<float4*>(om + (size_t)(v + 1) * DIM)[c], o);
}

// ---------------------------------------------------------------------------
// Overflow fix-up (runs after each conv pair; lists are empty in practice).
// ---------------------------------------------------------------------------
__global__ void k_ovf(const float* __restrict__ xs, const float* __restrict__ xt, int nT) {
    int ns = min(g_ovfn_s, OVF_CAP);
    for (int i = threadIdx.x; i < ns; i += blockDim.x) {
        int2 p = g_ovf_s[i];
        float iv = g_invdeg_s[p.x];
        const float* src = xs + (size_t)(p.y + 1) * DIM;
        float* dst = g_means + (size_t)(p.x + 1) * DIM;
        for (int c2 = 0; c2 < DIM; c2++) atomicAdd(&dst[c2], src[c2] * iv);
    }
    int nt = min(g_ovfn_t, OVF_CAP);
    for (int i = threadIdx.x; i < nt; i += blockDim.x) {
        int2 p = g_ovf_t[i];
        if (p.x >= nT) continue;
        float iv = g_invdeg_t[p.x];
        const float* src = xt + (size_t)(p.y + 1) * DIM;
        float* dst = g_meant + (size_t)(p.x + 1) * DIM;
        for (int c2 = 0; c2 < DIM; c2++) atomicAdd(&dst[c2], src[c2] * iv);
    }
}

// ---------------------------------------------------------------------------
// Combine: users get mix GEMM ue=[ms|mt]@W^T+b (fp32, float4-packed smem W).
// Mean reads evict-first. Next-layer tables g_xs/g_xt default (resident);
// g_embs slice evict-first (pred-only). Optional link mask on last layer.
// ---------------------------------------------------------------------------
__global__ void __launch_bounds__(256)
k_combine(const float* __restrict__ mix_w, const float* __restrict__ mix_b,
          int layer, int write_next, const int* __restrict__ need, int use_mask) {
    // WT4[k2*32 + ln] = { W[ln][2k2], W[ln+32][2k2], W[ln][2k2+1], W[ln+32][2k2+1] }
    __shared__ float4 WT4[64 * 32];    // 32 KB
    __shared__ float  BB[64];

    const float* W = mix_w + (size_t)layer * 64 * 128;
    for (int i = threadIdx.x; i < 64 * 32; i += blockDim.x) {
        int k2 = i >> 5, ln = i & 31;
        WT4[i] = make_float4(W[ln * 128 + 2 * k2],     W[(ln + 32) * 128 + 2 * k2],
                             W[ln * 128 + 2 * k2 + 1], W[(ln + 32) * 128 + 2 * k2 + 1]);
    }
    if (threadIdx.x < 64) BB[threadIdx.x] = mix_b[layer * 64 + threadIdx.x];
    __syncthreads();

    int lane = threadIdx.x & 31;
    int warp = threadIdx.x >> 5;
    int wpb  = blockDim.x >> 5;

    for (int v = blockIdx.x * wpb + warp; v < N_NODES; v += gridDim.x * wpb) {
        if (use_mask && __ldg(&need[v]) == 0) continue;   // warp-uniform
        size_t base = (size_t)(v + 1) * DIM;

        float ms0 = __ldcs(&g_means[base + lane]);
        float ms1 = __ldcs(&g_means[base + 32 + lane]);
        float mt0 = __ldcs(&g_meant[base + lane]);
        float mt1 = __ldcs(&g_meant[base + 32 + lane]);

        float o0, o1, t0, t1;
        if (v < N_USERS) {
            float a0 = BB[lane], a1 = BB[lane + 32];
            #pragma unroll
            for (int k2 = 0; k2 < 16; k2++) {
                float m0 = __shfl_sync(0xffffffffu, ms0, 2 * k2);
                float m1 = __shfl_sync(0xffffffffu, ms0, 2 * k2 + 1);
                float4 qv = WT4[k2 * 32 + lane];
                a0 += m0 * qv.x + m1 * qv.z;
                a1 += m0 * qv.y + m1 * qv.w;
            }
            #pragma unroll
            for (int k2 = 0; k2 < 16; k2++) {
                float m0 = __shfl_sync(0xffffffffu, ms1, 2 * k2);
                float m1 = __shfl_sync(0xffffffffu, ms1, 2 * k2 + 1);
                float4 qv = WT4[(16 + k2) * 32 + lane];
                a0 += m0 * qv.x + m1 * qv.z;
                a1 += m0 * qv.y + m1 * qv.w;
            }
            #pragma unroll
            for (int k2 = 0; k2 < 16; k2++) {
                float m0 = __shfl_sync(0xffffffffu, mt0, 2 * k2);
                float m1 = __shfl_sync(0xffffffffu, mt0, 2 * k2 + 1);
                float4 qv = WT4[(32 + k2) * 32 + lane];
                a0 += m0 * qv.x + m1 * qv.z;
                a1 += m0 * qv.y + m1 * qv.w;
            }
            #pragma unroll
            for (int k2 = 0; k2 < 16; k2++) {
                float m0 = __shfl_sync(0xffffffffu, mt1, 2 * k2);
                float m1 = __shfl_sync(0xffffffffu, mt1, 2 * k2 + 1);
                float4 qv = WT4[(48 + k2) * 32 + lane];
                a0 += m0 * qv.x + m1 * qv.z;
                a1 += m0 * qv.y + m1 * qv.w;
            }
            o0 = a0; o1 = a1; t0 = a0; t1 = a1;
        } else {
            o0 = ms0; o1 = ms1; t0 = mt0; t1 = mt1;
        }

        if (write_next) {
            g_xs[base + lane]      = o0;            // default policy: resident
            g_xs[base + 32 + lane] = o1;
            g_xt[base + lane]      = t0;
            g_xt[base + 32 + lane] = t1;
        }
        float* er = g_embs + (size_t)(v + 1) * EMB_COLS + (size_t)(layer + 1) * DIM;
        __stcs(&er[lane],      o0);                 // pred-only: evict-first
        __stcs(&er[lane + 32], o1);
    }
}

// ---------------------------------------------------------------------------
// Prediction head: warp per link, float4 loads (1-based rows, fp32).
// ---------------------------------------------------------------------------
__global__ void k_pred(const int* __restrict__ link,
                       const float* __restrict__ pred_w,
                       const float* __restrict__ pred_b,
                       float* __restrict__ out) {
    __shared__ float4 pw4[128];                       // 512 floats
    for (int i = threadIdx.x; i < 128; i += blockDim.x)
        pw4[i] = reinterpret_cast<const float4*>(pred_w)[i];
    __syncthreads();

    int lane = threadIdx.x & 31;
    int warp = threadIdx.x >> 5;
    int j = blockIdx.x * (blockDim.x >> 5) + warp;
    if (j >= N_LINK) return;

    int u  = __ldg(&link[j]) + 1;
    int it = __ldg(&link[N_LINK + j]) + 1;
    const float4* ue4 = reinterpret_cast<const float4*>(g_embs + (size_t)u  * EMB_COLS);
    const float4* ie4 = reinterpret_cast<const float4*>(g_embs + (size_t)it * EMB_COLS);

    float acc = 0.f;
    #pragma unroll
    for (int r = 0; r < 2; r++) {
        int idx = lane + r * 32;                      // 0..63
        float4 a = __ldg(&ue4[idx]);
        float4 w = pw4[idx];
        acc += a.x * w.x + a.y * w.y + a.z * w.z + a.w * w.w;
        float4 b = __ldg(&ie4[idx]);
        float4 w2 = pw4[64 + idx];
        acc += b.x * w2.x + b.y * w2.y + b.z * w2.z + b.w * w2.w;
    }

    #pragma unroll
    for (int o = 16; o > 0; o >>= 1) acc += __shfl_down_sync(0xffffffffu, acc, o);

    if (lane == 0) {
        float z = acc + pred_b[0];
        z = (z >= 0.f) ? z : 0.01f * z;
        out[j] = 1.f / (1.f + expf(-z));
    }
}

// ---------------------------------------------------------------------------
// Tail: restore zero state (counts + overflow counters) for the next call.
// g_need is set-only with identical values every call -> no clear needed.
// ---------------------------------------------------------------------------
__global__ void k_tail() {
    int stride = gridDim.x * blockDim.x;
    int t0 = blockIdx.x * blockDim.x + threadIdx.x;
    for (int i = t0; i < N_NODES; i += stride) { g_cnt_s[i] = 0; g_cnt_t[i] = 0; }
    if (t0 == 0) { g_ovfn_s = 0; g_ovfn_t = 0; }
}

// ---------------------------------------------------------------------------
// Launch.
// ---------------------------------------------------------------------------
extern "C" void kernel_launch(void* const* d_in, const int* in_sizes, int n_in,
                              void* d_out, int out_size) {
    const int*   sei    = (const int*)  d_in[0];
    const int*   tei    = (const int*)  d_in[1];
    const int*   link   = (const int*)  d_in[2];
    const float* emb    = (const float*)d_in[3];
    const float* mix_w  = (const float*)d_in[4];
    const float* mix_b  = (const float*)d_in[5];
    const float* pred_w = (const float*)d_in[6];
    const float* pred_b = (const float*)d_in[7];
    float*       out    = (float*)d_out;

    const int* s_src = sei;
    const int* s_dst = sei + E_EDGES;
    const int* t_src = tei;
    const int* t_dst = tei + E_EDGES;

    k_build<<<(E_EDGES + 255) / 256, 256>>>(s_src, s_dst, t_src, t_dst);
    k_prep <<<(N_NODES + 255) / 256, 256>>>(reinterpret_cast<const float4*>(emb), link);

    for (int l = 0; l < LAYERS; l++) {
        int last = (l == LAYERS - 1) ? 1 : 0;
        // source conv: dense g_xs -> g_means (last layer: linked nodes only)
        k_conv<<<(N_NODES / 2 * 32 + 255) / 256, 256>>>(
            g_xs, g_cnt_s, g_invdeg_s, g_ell_s, g_means, N_NODES, g_need, last);
        // target conv: layer 0 gathers g_xs (same emb table); else g_xt.
        // Last layer: only linked user rows are ever consumed.
        const float* xt = (l == 0) ? g_xs : g_xt;
        int          nT = last ? N_USERS : N_NODES;
        k_conv<<<(nT / 2 * 32 + 255) / 256, 256>>>(
            xt, g_cnt_t, g_invdeg_t, g_ell_t, g_meant, nT, g_need, last);

        k_ovf<<<1, 256>>>(g_xs, xt, nT);

        k_combine<<<2960, 256>>>(mix_w, mix_b, l, last ? 0 : 1, g_need, last);
    }

    k_pred<<<(N_LINK + 7) / 8, 256>>>(link, pred_w, pred_b, out);
    k_tail<<<4096, 256>>>();
}